// round 15
// baseline (speedup 1.0000x reference)
#include <cuda_runtime.h>
#include <cuda_fp16.h>
#include <cstdint>

// Problem constants
#define Bn 16
#define Sn 1024
#define Dn 128
#define Hn 8
#define DHn 16
#define DFFn 512
#define Ln 3
#define NCn 6
#define Mrows (Bn * Sn)   // 16384

// ============================================================================
// Helpers
// ============================================================================
__device__ __forceinline__ uint32_t f16x2(float a, float b) {
    __half2 h = __floats2half2_rn(a, b);
    return *(uint32_t*)&h;
}
__device__ __forceinline__ uint32_t ex2h2(uint32_t x) {
    uint32_t y;
    asm("ex2.approx.f16x2 %0, %1;" : "=r"(y) : "r"(x));
    return y;
}
__device__ __forceinline__ uint32_t smem_u32(const void* p) {
    uint32_t a;
    asm("{ .reg .u64 t; cvta.to.shared.u64 t, %1; cvt.u32.u64 %0, t; }"
        : "=r"(a) : "l"(p));
    return a;
}
__device__ __forceinline__ void cp16(uint32_t dst, const void* src) {
    asm volatile("cp.async.cg.shared.global [%0], [%1], 16;"
                 :: "r"(dst), "l"(src));
}
#define CP_COMMIT() asm volatile("cp.async.commit_group;" ::: "memory")
#define CP_WAIT1()  asm volatile("cp.async.wait_group 1;" ::: "memory")
#define CP_WAIT0()  asm volatile("cp.async.wait_group 0;" ::: "memory")

__device__ __forceinline__ void mma_f16(float* d, uint32_t a0, uint32_t a1,
                                        uint32_t a2, uint32_t a3,
                                        uint32_t b0, uint32_t b1) {
    asm volatile(
        "mma.sync.aligned.m16n8k16.row.col.f32.f16.f16.f32 "
        "{%0,%1,%2,%3},{%4,%5,%6,%7},{%8,%9},{%0,%1,%2,%3};"
        : "+f"(d[0]), "+f"(d[1]), "+f"(d[2]), "+f"(d[3])
        : "r"(a0), "r"(a1), "r"(a2), "r"(a3), "r"(b0), "r"(b1));
}
// MMA with broadcast constant c operand (initializes d = A*B + c, no pre-init)
__device__ __forceinline__ void mma_f16_init(float* d, uint32_t a0, uint32_t a1,
                                             uint32_t a2, uint32_t a3,
                                             uint32_t b0, uint32_t b1, float c) {
    asm volatile(
        "mma.sync.aligned.m16n8k16.row.col.f32.f16.f16.f32 "
        "{%0,%1,%2,%3},{%4,%5,%6,%7},{%8,%9},{%10,%10,%10,%10};"
        : "=f"(d[0]), "=f"(d[1]), "=f"(d[2]), "=f"(d[3])
        : "r"(a0), "r"(a1), "r"(a2), "r"(a3), "r"(b0), "r"(b1), "f"(c));
}
#define LDSM4(r, addr) \
    asm volatile("ldmatrix.sync.aligned.m8n8.x4.shared.b16 {%0,%1,%2,%3},[%4];" \
        : "=r"((r)[0]), "=r"((r)[1]), "=r"((r)[2]), "=r"((r)[3]) : "r"(addr))
#define LDSM4T(r, addr) \
    asm volatile("ldmatrix.sync.aligned.m8n8.x4.trans.shared.b16 {%0,%1,%2,%3},[%4];" \
        : "=r"((r)[0]), "=r"((r)[1]), "=r"((r)[2]), "=r"((r)[3]) : "r"(addr))

// ============================================================================
// Device-global scratch
// ============================================================================
__device__ float  g_x[Mrows * Dn];
__device__ __half g_xh[Mrows * Dn];
__device__ __half g_q[Mrows * Dn];       // pre-scaled by 0.25*log2(e)
__device__ __half g_k[Mrows * Dn];
__device__ __half g_v[Mrows * Dn];
__device__ float  g_o[Mrows * Dn];
__device__ float  g_opart[2 * Mrows * Dn];   // ffn2 split-K=2 partials
__device__ __half g_h[Mrows * DFFn];
__device__ __half g_wqkv[Ln * 3 * Dn * Dn];   // f16, [N,K] transposed
__device__ __half g_w1[Ln * DFFn * Dn];
__device__ __half g_w2[Ln * Dn * DFFn];
__device__ float  g_bqkv[Ln * 3 * Dn];

// ============================================================================
// Prep kernels (unchanged — known correct)
// ============================================================================
#define PREP_QKV (3 * Dn * Dn)
#define PREP_W   (Dn * DFFn)
#define PREP_PER_LAYER (PREP_QKV + 2 * PREP_W)
#define PREP_TOTAL (Ln * PREP_PER_LAYER)

__global__ void prep_weights(const float* __restrict__ Wq, const float* __restrict__ Wk,
                             const float* __restrict__ Wv, const float* __restrict__ W1,
                             const float* __restrict__ W2) {
    int idx = blockIdx.x * blockDim.x + threadIdx.x;
    if (idx >= PREP_TOTAL) return;
    int l = idx / PREP_PER_LAYER;
    int r = idx % PREP_PER_LAYER;
    float v;
    __half* dst_arr;
    int dst;
    if (r < PREP_QKV) {
        int which = r / (Dn * Dn);
        int e = r % (Dn * Dn);
        int n = e / Dn, k = e % Dn;
        const float* W = which == 0 ? Wq : (which == 1 ? Wk : Wv);
        v = W[l * Dn * Dn + k * Dn + n];
        dst = l * PREP_QKV + which * Dn * Dn + n * Dn + k;
        dst_arr = g_wqkv;
    } else if (r < PREP_QKV + PREP_W) {
        int e = r - PREP_QKV;
        int n = e / Dn, k = e % Dn;
        v = W1[l * PREP_W + k * DFFn + n];
        dst = l * PREP_W + n * Dn + k;
        dst_arr = g_w1;
    } else {
        int e = r - PREP_QKV - PREP_W;
        int n = e / DFFn, k = e % DFFn;
        v = W2[l * PREP_W + k * Dn + n];
        dst = l * PREP_W + n * DFFn + k;
        dst_arr = g_w2;
    }
    dst_arr[dst] = __float2half_rn(v);
}

__global__ void prep_bias(const float* __restrict__ bq, const float* __restrict__ bk,
                          const float* __restrict__ bv) {
    int idx = blockIdx.x * blockDim.x + threadIdx.x;
    if (idx >= Ln * 3 * Dn) return;
    int l = idx / (3 * Dn);
    int r = idx % (3 * Dn);
    int which = r / Dn, n = r % Dn;
    const float* b = which == 0 ? bq : (which == 1 ? bk : bv);
    g_bqkv[idx] = b[l * Dn + n];
}

__global__ void prep_input(const float* __restrict__ x) {
    int i = (blockIdx.x * blockDim.x + threadIdx.x) * 4;
    float4 v = *(const float4*)&x[i];
    *(float4*)&g_x[i] = v;
    *(uint32_t*)&g_xh[i]     = f16x2(v.x, v.y);
    *(uint32_t*)&g_xh[i + 2] = f16x2(v.z, v.w);
}

// ============================================================================
// MMA GEMM (R10 structure, unchanged): tile 128(M) x 64(N), f16 single-pass,
// 2-stage cp.async pipeline, 3 CTAs/SM.
// MODE 0 = QKV (ReLU; nt>>1: 0->Q pre-scaled / 1->K / 2->V)
// MODE 1 = FFN1 (ReLU; f16 out, ldc=512)
// MODE 2 = FFN2 (no act; split-K=2 over z, K=256/CTA; fp32 partials)
// smem: stage = A(18432)+B(9216) = 27648; 2 stages = 55296
// ============================================================================
#define GARR_A 18432
#define GARR_B 9216
#define GSTAGE (GARR_A + GARR_B)   // 27648
#define QSCALE 0.36067376022224085f   // 0.25 * log2(e)

template <int MODE>
__global__ __launch_bounds__(256, 3)
void gemm_mma(const __half* __restrict__ A, const __half* __restrict__ Bw,
              const float* __restrict__ bias,
              __half* __restrict__ qh, __half* __restrict__ kk,
              __half* __restrict__ vv,
              __half* __restrict__ oh, float* __restrict__ of,
              int K, int ldc) {
    extern __shared__ __align__(16) char smem[];
    const uint32_t sb = smem_u32(smem);

    const int tid = threadIdx.x, lane = tid & 31, wid = tid >> 5;
    const int nt = blockIdx.x;
    const int bm = blockIdx.y * 128;
    const int nb = nt * 64;
    const int kz = (MODE == 2) ? blockIdx.z : 0;
    const int kbase = (MODE == 2) ? kz * 256 : 0;
    const int nchunks = (MODE == 2) ? 4 : (K >> 6);
    const int wm = (wid & 3) * 32, wn = (wid >> 2) * 32;
    const int gid = lane >> 2, qd = lane & 3;

    float acc[2][4][4];
#pragma unroll
    for (int i = 0; i < 2; i++)
#pragma unroll
        for (int j = 0; j < 4; j++)
#pragma unroll
            for (int c = 0; c < 4; c++) acc[i][j][c] = 0.f;

    const uint32_t a_off = (uint32_t)((lane & 15) * 144 + ((lane >> 4) << 4));
    const uint32_t b_off = (uint32_t)((((lane & 7) + ((lane >> 4) & 1) * 8)) * 144 +
                                      ((lane >> 3) & 1) * 16);

    // 6 cp.async per thread per chunk (A: 1024, B: 512 transfers)
    auto issue = [&](int ch) {
        const int k0 = kbase + (ch << 6);
        const uint32_t base = sb + (uint32_t)(ch & 1) * GSTAGE;
#pragma unroll
        for (int t = 0; t < 4; t++) {
            int id = t * 256 + tid;
            int r = id >> 3, c = id & 7;
            cp16(base + (uint32_t)(r * 144 + c * 16),
                 A + (size_t)(bm + r) * K + k0 + c * 8);
        }
#pragma unroll
        for (int t = 0; t < 2; t++) {
            int id = t * 256 + tid;
            int r = id >> 3, c = id & 7;
            cp16(base + GARR_A + (uint32_t)(r * 144 + c * 16),
                 Bw + (size_t)(nb + r) * K + k0 + c * 8);
        }
        CP_COMMIT();
    };

    issue(0);
    for (int ch = 0; ch < nchunks; ch++) {
        if (ch + 1 < nchunks) { issue(ch + 1); CP_WAIT1(); }
        else                  { CP_WAIT0(); }
        __syncthreads();

        const uint32_t stg = sb + (uint32_t)(ch & 1) * GSTAGE;
        const uint32_t SA = stg, SB = stg + GARR_A;

#pragma unroll
        for (int ks = 0; ks < 4; ks++) {
            const uint32_t kb = ks * 32;
            uint32_t ah[2][4], bb[2][4];
            LDSM4(ah[0], SA + a_off + (wm) * 144 + kb);
            LDSM4(ah[1], SA + a_off + (wm + 16) * 144 + kb);
            LDSM4(bb[0], SB + b_off + (wn) * 144 + kb);
            LDSM4(bb[1], SB + b_off + (wn + 16) * 144 + kb);
#pragma unroll
            for (int mf = 0; mf < 2; mf++)
#pragma unroll
                for (int j = 0; j < 4; j++)
                    mma_f16(acc[mf][j], ah[mf][0], ah[mf][1], ah[mf][2], ah[mf][3],
                            bb[j >> 1][(j & 1) * 2], bb[j >> 1][(j & 1) * 2 + 1]);
        }
        // trailing sync only needed if iteration ch+1 will issue chunk ch+2
        if (ch + 2 < nchunks) __syncthreads();
    }

    // ---- epilogue
#pragma unroll
    for (int mf = 0; mf < 2; mf++) {
        const int r0g = bm + wm + mf * 16 + gid;
        const int r1g = r0g + 8;
#pragma unroll
        for (int j = 0; j < 4; j++) {
            const int cl = wn + j * 8 + qd * 2;
            float2 bs;
            if (MODE == 2 && kz != 0) bs = make_float2(0.f, 0.f);
            else bs = *(const float2*)(bias + nb + cl);
            float v00 = acc[mf][j][0] + bs.x, v01 = acc[mf][j][1] + bs.y;
            float v10 = acc[mf][j][2] + bs.x, v11 = acc[mf][j][3] + bs.y;
            if (MODE != 2) {
                v00 = fmaxf(v00, 0.f); v01 = fmaxf(v01, 0.f);
                v10 = fmaxf(v10, 0.f); v11 = fmaxf(v11, 0.f);
            }
            if (MODE == 0) {
                const int which = nt >> 1;
                const int mc = (nt & 1) * 64 + cl;
                size_t o0 = (size_t)r0g * 128 + mc;
                size_t o1 = (size_t)r1g * 128 + mc;
                if (which == 0) {
                    *(uint32_t*)(qh + o0) = f16x2(v00 * QSCALE, v01 * QSCALE);
                    *(uint32_t*)(qh + o1) = f16x2(v10 * QSCALE, v11 * QSCALE);
                } else if (which == 1) {
                    *(uint32_t*)(kk + o0) = f16x2(v00, v01);
                    *(uint32_t*)(kk + o1) = f16x2(v10, v11);
                } else {
                    *(uint32_t*)(vv + o0) = f16x2(v00, v01);
                    *(uint32_t*)(vv + o1) = f16x2(v10, v11);
                }
            } else if (MODE == 1) {
                size_t o0 = (size_t)r0g * ldc + nb + cl;
                size_t o1 = (size_t)r1g * ldc + nb + cl;
                *(uint32_t*)(oh + o0) = f16x2(v00, v01);
                *(uint32_t*)(oh + o1) = f16x2(v10, v11);
            } else {
                float* C = of + (size_t)kz * (Mrows * Dn);
                *(float2*)(C + (size_t)r0g * ldc + nb + cl) = make_float2(v00, v01);
                *(float2*)(C + (size_t)r1g * ldc + nb + cl) = make_float2(v10, v11);
            }
        }
    }
}

// ============================================================================
// Flash attention v7: 128-key staged tiles (two 64-key halves), 3-stage ring,
// sacc init folded into the QK MMA via constant-c operand (zero init movs),
// all-f16 single-pass, Q pre-scaled, shifted (-8) no-max softmax via ex2.f16x2,
// l via MMA ones. 256 threads, 128 queries/CTA, 2 CTAs/SM.
// smem: 3 stages x (K 6144 + V 6144) = 36864 B static
// ============================================================================
#define AARR 6144                  // 128 keys x 48 B
#define ASTG (2 * AARR)            // 12288 per stage
#define ONES_H2 0x3C003C00u

__global__ __launch_bounds__(256, 2)
void attn_mma(const __half* __restrict__ Qg, const __half* __restrict__ Kg,
              const __half* __restrict__ Vg, float* __restrict__ O) {
    static __shared__ __align__(16) char sm[3 * ASTG];
    const uint32_t sb = smem_u32(sm);

    const int b = blockIdx.z, h = blockIdx.y, q0 = blockIdx.x * 128;
    const int tid = threadIdx.x, lane = tid & 31, w = tid >> 5;
    const int gid = lane >> 2, qd = lane & 3;

    const uint32_t kb_off = (uint32_t)(((lane & 7) + ((lane >> 4) & 1) * 8) * 48 +
                                       ((lane >> 3) & 1) * 16);
    const uint32_t vb_off = (uint32_t)(((lane & 7) + ((lane >> 3) & 1) * 8) * 48 +
                                       ((lane >> 4) & 1) * 16);

    // ---- Q fragments (pre-scaled f16 pairs)
    uint32_t aq[4];
    {
        const int r0 = q0 + w * 16 + gid;
        const int c0 = h * 16 + qd * 2;
        const __half* q0p = Qg + (size_t)(b * Sn + r0) * Dn;
        const __half* q1p = q0p + (size_t)8 * Dn;
        aq[0] = *(const uint32_t*)(q0p + c0);
        aq[1] = *(const uint32_t*)(q1p + c0);
        aq[2] = *(const uint32_t*)(q0p + c0 + 8);
        aq[3] = *(const uint32_t*)(q1p + c0 + 8);
    }

    // 512 cp.async per 128-key tile: K 256 + V 256 (2 per thread)
    auto issue = [&](int kt) {
        const int kbase = kt * 128;
        const uint32_t base = sb + (uint32_t)(kt % 3) * ASTG;
#pragma unroll
        for (int t = 0; t < 2; t++) {
            int id = t * 256 + tid;
            int arr = id >> 8, rem = id & 255;
            int k = rem >> 1, c = rem & 1;
            const __half* p = arr ? Vg : Kg;
            cp16(base + (uint32_t)arr * AARR + (uint32_t)(k * 48 + c * 16),
                 p + (size_t)(b * Sn + kbase + k) * Dn + h * 16 + c * 8);
        }
        CP_COMMIT();
    };

    float oacc[2][4] = {};
    float lacc[4] = {};
    const float cm8 = -8.f;

    issue(0);
    for (int kt = 0; kt < 8; kt++) {
        if (kt + 1 < 8) { issue(kt + 1); CP_WAIT1(); }
        else            { CP_WAIT0(); }
        __syncthreads();   // single sync per 128-key tile (3-stage ring)

        const uint32_t stg = sb + (uint32_t)(kt % 3) * ASTG;

#pragma unroll
        for (int half = 0; half < 2; half++) {
            const uint32_t sK = stg + (uint32_t)half * 3072;
            const uint32_t sV = stg + AARR + (uint32_t)half * 3072;

            // ---- QK^T (1 pass); init to -8 via MMA c-operand (no movs)
            float sacc[8][4];
            {
                uint32_t bb[4][4];
#pragma unroll
                for (int p = 0; p < 4; p++) LDSM4(bb[p], sK + kb_off + p * 16 * 48);
#pragma unroll
                for (int j = 0; j < 8; j++)
                    mma_f16_init(sacc[j], aq[0], aq[1], aq[2], aq[3],
                                 bb[j >> 1][(j & 1) * 2], bb[j >> 1][(j & 1) * 2 + 1],
                                 cm8);
            }

            // ---- P = 2^(s-8) as packed f16x2 (A-frag order)
            uint32_t ap[4][4];
#pragma unroll
            for (int t = 0; t < 4; t++) {
                const int e0 = 2 * t, e1 = 2 * t + 1;
                ap[t][0] = ex2h2(f16x2(sacc[e0][0], sacc[e0][1]));
                ap[t][1] = ex2h2(f16x2(sacc[e0][2], sacc[e0][3]));
                ap[t][2] = ex2h2(f16x2(sacc[e1][0], sacc[e1][1]));
                ap[t][3] = ex2h2(f16x2(sacc[e1][2], sacc[e1][3]));
            }

            // ---- l += P @ ones (row sums via MMA)
#pragma unroll
            for (int t = 0; t < 4; t++)
                mma_f16(lacc, ap[t][0], ap[t][1], ap[t][2], ap[t][3],
                        ONES_H2, ONES_H2);

            // ---- PV (1 pass)
            {
                uint32_t vb[4][4];
#pragma unroll
                for (int t = 0; t < 4; t++) LDSM4T(vb[t], sV + vb_off + t * 16 * 48);
#pragma unroll
                for (int t = 0; t < 4; t++) {
                    mma_f16(oacc[0], ap[t][0], ap[t][1], ap[t][2], ap[t][3],
                            vb[t][0], vb[t][1]);
                    mma_f16(oacc[1], ap[t][0], ap[t][1], ap[t][2], ap[t][3],
                            vb[t][2], vb[t][3]);
                }
            }
        }
    }

    // ---- write O (lacc cols are replicated row sums: [0]=row r0, [2]=row r1)
    const float inv0 = 1.f / lacc[0], inv1 = 1.f / lacc[2];
    const int r0 = q0 + w * 16 + gid, r1 = r0 + 8;
    const int c = h * 16 + qd * 2;
#pragma unroll
    for (int nf = 0; nf < 2; nf++) {
        *(float2*)&O[(size_t)(b * Sn + r0) * Dn + c + nf * 8] =
            make_float2(oacc[nf][0] * inv0, oacc[nf][1] * inv0);
        *(float2*)&O[(size_t)(b * Sn + r1) * Dn + c + nf * 8] =
            make_float2(oacc[nf][2] * inv1, oacc[nf][3] * inv1);
    }
}

// ============================================================================
// Residual add + LayerNorm (warp-per-row); NPART partial fp32 buffers summed.
// ============================================================================
template <int NPART>
__global__ __launch_bounds__(256)
void add_ln_kernel(const float* __restrict__ inp, float* __restrict__ x,
                   __half* __restrict__ xh,
                   const float* __restrict__ gam, const float* __restrict__ bet,
                   float eps) {
    const int lane = threadIdx.x & 31;
    const int row = blockIdx.x * 8 + (threadIdx.x >> 5);
    const int c0 = lane * 4;
    const size_t base = (size_t)row * Dn + c0;

    float4 a = *(const float4*)&inp[base];
#pragma unroll
    for (int p = 1; p < NPART; p++) {
        float4 ap = *(const float4*)&inp[(size_t)p * (Mrows * Dn) + base];
        a.x += ap.x; a.y += ap.y; a.z += ap.z; a.w += ap.w;
    }
    float4 bx = *(const float4*)&x[base];
    float v[4] = {a.x + bx.x, a.y + bx.y, a.z + bx.z, a.w + bx.w};

    float s = v[0] + v[1] + v[2] + v[3];
#pragma unroll
    for (int o = 16; o > 0; o >>= 1) s += __shfl_xor_sync(0xffffffffu, s, o);
    const float mu = s * (1.f / Dn);

    float d[4] = {v[0] - mu, v[1] - mu, v[2] - mu, v[3] - mu};
    float s2 = d[0] * d[0] + d[1] * d[1] + d[2] * d[2] + d[3] * d[3];
#pragma unroll
    for (int o = 16; o > 0; o >>= 1) s2 += __shfl_xor_sync(0xffffffffu, s2, o);
    const float r = rsqrtf(s2 * (1.f / Dn) + eps);

    float4 g = *(const float4*)&gam[c0];
    float4 be = *(const float4*)&bet[c0];
    float y0 = fmaf(g.x * d[0], r, be.x);
    float y1 = fmaf(g.y * d[1], r, be.y);
    float y2 = fmaf(g.z * d[2], r, be.z);
    float y3 = fmaf(g.w * d[3], r, be.w);

    *(float4*)&x[base] = make_float4(y0, y1, y2, y3);
    *(uint32_t*)&xh[base]     = f16x2(y0, y1);
    *(uint32_t*)&xh[base + 2] = f16x2(y2, y3);
}

// ============================================================================
// Classifier: warp per row, N=6 (fp32, exact)
// ============================================================================
__global__ __launch_bounds__(256)
void classifier_kernel(const float* __restrict__ x, const float* __restrict__ W,
                       const float* __restrict__ bias, float* __restrict__ out) {
    const int warp = threadIdx.x >> 5;
    const int lane = threadIdx.x & 31;
    const int row = blockIdx.x * 8 + warp;

    float acc[NCn] = {};
    for (int d = lane; d < Dn; d += 32) {
        float xv = x[(size_t)row * Dn + d];
#pragma unroll
        for (int c = 0; c < NCn; c++) acc[c] = fmaf(xv, W[d * NCn + c], acc[c]);
    }
#pragma unroll
    for (int c = 0; c < NCn; c++) {
#pragma unroll
        for (int o = 16; o > 0; o >>= 1)
            acc[c] += __shfl_down_sync(0xffffffffu, acc[c], o);
    }
    if (lane == 0) {
#pragma unroll
        for (int c = 0; c < NCn; c++) out[(size_t)row * NCn + c] = acc[c] + bias[c];
    }
}

// ============================================================================
// kernel_launch
// ============================================================================
extern "C" void kernel_launch(void* const* d_in, const int* in_sizes, int n_in,
                              void* d_out, int out_size) {
    const float* x    = (const float*)d_in[0];
    const float* Wq   = (const float*)d_in[1];
    const float* bq   = (const float*)d_in[2];
    const float* Wk   = (const float*)d_in[3];
    const float* bk   = (const float*)d_in[4];
    const float* Wv   = (const float*)d_in[5];
    const float* bv   = (const float*)d_in[6];
    const float* ln1g = (const float*)d_in[7];
    const float* ln1b = (const float*)d_in[8];
    const float* W1   = (const float*)d_in[9];
    const float* b1   = (const float*)d_in[10];
    const float* W2   = (const float*)d_in[11];
    const float* b2   = (const float*)d_in[12];
    const float* ln2g = (const float*)d_in[13];
    const float* ln2b = (const float*)d_in[14];
    const float* Wout = (const float*)d_in[15];
    const float* bout = (const float*)d_in[16];
    float* out = (float*)d_out;

    float *gx, *go, *gopart, *gbqkv;
    __half *gxh, *gq, *gk, *gv, *gh;
    __half *wqkv, *w1, *w2;
    cudaGetSymbolAddress((void**)&gx, g_x);
    cudaGetSymbolAddress((void**)&go, g_o);
    cudaGetSymbolAddress((void**)&gopart, g_opart);
    cudaGetSymbolAddress((void**)&gxh, g_xh);
    cudaGetSymbolAddress((void**)&gq, g_q);
    cudaGetSymbolAddress((void**)&gk, g_k);
    cudaGetSymbolAddress((void**)&gv, g_v);
    cudaGetSymbolAddress((void**)&gh, g_h);
    cudaGetSymbolAddress((void**)&wqkv, g_wqkv);
    cudaGetSymbolAddress((void**)&w1, g_w1);
    cudaGetSymbolAddress((void**)&w2, g_w2);
    cudaGetSymbolAddress((void**)&gbqkv, g_bqkv);

    const int SMEM_GEMM = 2 * GSTAGE;   // 55296
    cudaFuncSetAttribute(gemm_mma<0>, cudaFuncAttributeMaxDynamicSharedMemorySize, SMEM_GEMM);
    cudaFuncSetAttribute(gemm_mma<1>, cudaFuncAttributeMaxDynamicSharedMemorySize, SMEM_GEMM);
    cudaFuncSetAttribute(gemm_mma<2>, cudaFuncAttributeMaxDynamicSharedMemorySize, SMEM_GEMM);

    prep_weights<<<(PREP_TOTAL + 255) / 256, 256>>>(Wq, Wk, Wv, W1, W2);
    prep_bias<<<(Ln * 3 * Dn + 255) / 256, 256>>>(bq, bk, bv);
    prep_input<<<(Mrows * Dn / 4 + 255) / 256, 256>>>(x);

    const dim3 qkvGrid(6, Mrows / 128);          // 768 CTAs
    const dim3 f1Grid(8, Mrows / 128);           // 1024 CTAs
    const dim3 f2Grid(2, Mrows / 128, 2);        // 512 CTAs, split-K=2
    const dim3 attnGrid(Sn / 128, Hn, Bn);       // 1024 CTAs

    for (int l = 0; l < Ln; l++) {
        gemm_mma<0><<<qkvGrid, 256, SMEM_GEMM>>>(
            gxh, wqkv + (size_t)l * PREP_QKV, gbqkv + l * 3 * Dn,
            gq, gk, gv, nullptr, nullptr, Dn, Dn);

        attn_mma<<<attnGrid, 256>>>(gq, gk, gv, go);

        add_ln_kernel<1><<<Mrows / 8, 256>>>(go, gx, gxh,
                                             ln1g + l * Dn, ln1b + l * Dn, 1e-8f);

        gemm_mma<1><<<f1Grid, 256, SMEM_GEMM>>>(
            gxh, w1 + (size_t)l * PREP_W, b1 + l * DFFn,
            nullptr, nullptr, nullptr, gh, nullptr, Dn, DFFn);

        gemm_mma<2><<<f2Grid, 256, SMEM_GEMM>>>(
            gh, w2 + (size_t)l * PREP_W, b2 + l * Dn,
            nullptr, nullptr, nullptr, nullptr, gopart, DFFn, Dn);

        add_ln_kernel<2><<<Mrows / 8, 256>>>(gopart, gx, gxh,
                                             ln2g + l * Dn, ln2b + l * Dn, 1e-6f);
    }

    classifier_kernel<<<Mrows / 8, 256>>>(gx, Wout, bout, out);
}

// round 16
// speedup vs baseline: 1.0020x; 1.0020x over previous
#include <cuda_runtime.h>
#include <cuda_fp16.h>
#include <cstdint>

// Problem constants
#define Bn 16
#define Sn 1024
#define Dn 128
#define Hn 8
#define DHn 16
#define DFFn 512
#define Ln 3
#define NCn 6
#define Mrows (Bn * Sn)   // 16384

// ============================================================================
// Helpers
// ============================================================================
__device__ __forceinline__ uint32_t f16x2(float a, float b) {
    __half2 h = __floats2half2_rn(a, b);
    return *(uint32_t*)&h;
}
__device__ __forceinline__ uint32_t ex2h2(uint32_t x) {
    uint32_t y;
    asm("ex2.approx.f16x2 %0, %1;" : "=r"(y) : "r"(x));
    return y;
}
__device__ __forceinline__ uint32_t smem_u32(const void* p) {
    uint32_t a;
    asm("{ .reg .u64 t; cvta.to.shared.u64 t, %1; cvt.u32.u64 %0, t; }"
        : "=r"(a) : "l"(p));
    return a;
}
__device__ __forceinline__ void cp16(uint32_t dst, const void* src) {
    asm volatile("cp.async.cg.shared.global [%0], [%1], 16;"
                 :: "r"(dst), "l"(src));
}
#define CP_COMMIT() asm volatile("cp.async.commit_group;" ::: "memory")
#define CP_WAIT1()  asm volatile("cp.async.wait_group 1;" ::: "memory")
#define CP_WAIT0()  asm volatile("cp.async.wait_group 0;" ::: "memory")

__device__ __forceinline__ void mma_f16(float* d, uint32_t a0, uint32_t a1,
                                        uint32_t a2, uint32_t a3,
                                        uint32_t b0, uint32_t b1) {
    asm volatile(
        "mma.sync.aligned.m16n8k16.row.col.f32.f16.f16.f32 "
        "{%0,%1,%2,%3},{%4,%5,%6,%7},{%8,%9},{%0,%1,%2,%3};"
        : "+f"(d[0]), "+f"(d[1]), "+f"(d[2]), "+f"(d[3])
        : "r"(a0), "r"(a1), "r"(a2), "r"(a3), "r"(b0), "r"(b1));
}
#define LDSM4(r, addr) \
    asm volatile("ldmatrix.sync.aligned.m8n8.x4.shared.b16 {%0,%1,%2,%3},[%4];" \
        : "=r"((r)[0]), "=r"((r)[1]), "=r"((r)[2]), "=r"((r)[3]) : "r"(addr))
#define LDSM4T(r, addr) \
    asm volatile("ldmatrix.sync.aligned.m8n8.x4.trans.shared.b16 {%0,%1,%2,%3},[%4];" \
        : "=r"((r)[0]), "=r"((r)[1]), "=r"((r)[2]), "=r"((r)[3]) : "r"(addr))

// ============================================================================
// Device-global scratch
// ============================================================================
__device__ float  g_x[Mrows * Dn];
__device__ __half g_xh[Mrows * Dn];
__device__ __half g_q[Mrows * Dn];       // pre-scaled by 0.25*log2(e)
__device__ __half g_k[Mrows * Dn];
__device__ __half g_v[Mrows * Dn];
__device__ float  g_o[Mrows * Dn];
__device__ float  g_opart[2 * Mrows * Dn];   // ffn2 split-K=2 partials
__device__ __half g_h[Mrows * DFFn];
__device__ __half g_wqkv[Ln * 3 * Dn * Dn];   // f16, [N,K] transposed
__device__ __half g_w1[Ln * DFFn * Dn];
__device__ __half g_w2[Ln * Dn * DFFn];
__device__ float  g_bqkv[Ln * 3 * Dn];

// ============================================================================
// Prep kernels (unchanged — known correct)
// ============================================================================
#define PREP_QKV (3 * Dn * Dn)
#define PREP_W   (Dn * DFFn)
#define PREP_PER_LAYER (PREP_QKV + 2 * PREP_W)
#define PREP_TOTAL (Ln * PREP_PER_LAYER)

__global__ void prep_weights(const float* __restrict__ Wq, const float* __restrict__ Wk,
                             const float* __restrict__ Wv, const float* __restrict__ W1,
                             const float* __restrict__ W2) {
    int idx = blockIdx.x * blockDim.x + threadIdx.x;
    if (idx >= PREP_TOTAL) return;
    int l = idx / PREP_PER_LAYER;
    int r = idx % PREP_PER_LAYER;
    float v;
    __half* dst_arr;
    int dst;
    if (r < PREP_QKV) {
        int which = r / (Dn * Dn);
        int e = r % (Dn * Dn);
        int n = e / Dn, k = e % Dn;
        const float* W = which == 0 ? Wq : (which == 1 ? Wk : Wv);
        v = W[l * Dn * Dn + k * Dn + n];
        dst = l * PREP_QKV + which * Dn * Dn + n * Dn + k;
        dst_arr = g_wqkv;
    } else if (r < PREP_QKV + PREP_W) {
        int e = r - PREP_QKV;
        int n = e / Dn, k = e % Dn;
        v = W1[l * PREP_W + k * DFFn + n];
        dst = l * PREP_W + n * Dn + k;
        dst_arr = g_w1;
    } else {
        int e = r - PREP_QKV - PREP_W;
        int n = e / DFFn, k = e % DFFn;
        v = W2[l * PREP_W + k * Dn + n];
        dst = l * PREP_W + n * DFFn + k;
        dst_arr = g_w2;
    }
    dst_arr[dst] = __float2half_rn(v);
}

__global__ void prep_bias(const float* __restrict__ bq, const float* __restrict__ bk,
                          const float* __restrict__ bv) {
    int idx = blockIdx.x * blockDim.x + threadIdx.x;
    if (idx >= Ln * 3 * Dn) return;
    int l = idx / (3 * Dn);
    int r = idx % (3 * Dn);
    int which = r / Dn, n = r % Dn;
    const float* b = which == 0 ? bq : (which == 1 ? bk : bv);
    g_bqkv[idx] = b[l * Dn + n];
}

__global__ void prep_input(const float* __restrict__ x) {
    int i = (blockIdx.x * blockDim.x + threadIdx.x) * 4;
    float4 v = *(const float4*)&x[i];
    *(float4*)&g_x[i] = v;
    *(uint32_t*)&g_xh[i]     = f16x2(v.x, v.y);
    *(uint32_t*)&g_xh[i + 2] = f16x2(v.z, v.w);
}

// ============================================================================
// MMA GEMM (R10 structure): tile 128(M) x 64(N), f16 single-pass,
// 2-stage cp.async pipeline, NOW 4 CTAs/SM (smem 4x55.3KB = 221KB fits;
// forces <=64 regs — watch for spill).
// MODE 0 = QKV (ReLU; nt>>1: 0->Q pre-scaled / 1->K / 2->V)
// MODE 1 = FFN1 (ReLU; f16 out, ldc=512)
// MODE 2 = FFN2 (no act; split-K=2 over z, K=256/CTA; fp32 partials)
// smem: stage = A(18432)+B(9216) = 27648; 2 stages = 55296
// ============================================================================
#define GARR_A 18432
#define GARR_B 9216
#define GSTAGE (GARR_A + GARR_B)   // 27648
#define QSCALE 0.36067376022224085f   // 0.25 * log2(e)

template <int MODE>
__global__ __launch_bounds__(256, 4)
void gemm_mma(const __half* __restrict__ A, const __half* __restrict__ Bw,
              const float* __restrict__ bias,
              __half* __restrict__ qh, __half* __restrict__ kk,
              __half* __restrict__ vv,
              __half* __restrict__ oh, float* __restrict__ of,
              int K, int ldc) {
    extern __shared__ __align__(16) char smem[];
    const uint32_t sb = smem_u32(smem);

    const int tid = threadIdx.x, lane = tid & 31, wid = tid >> 5;
    const int nt = blockIdx.x;
    const int bm = blockIdx.y * 128;
    const int nb = nt * 64;
    const int kz = (MODE == 2) ? blockIdx.z : 0;
    const int kbase = (MODE == 2) ? kz * 256 : 0;
    const int nchunks = (MODE == 2) ? 4 : (K >> 6);
    const int wm = (wid & 3) * 32, wn = (wid >> 2) * 32;
    const int gid = lane >> 2, qd = lane & 3;

    float acc[2][4][4];
#pragma unroll
    for (int i = 0; i < 2; i++)
#pragma unroll
        for (int j = 0; j < 4; j++)
#pragma unroll
            for (int c = 0; c < 4; c++) acc[i][j][c] = 0.f;

    const uint32_t a_off = (uint32_t)((lane & 15) * 144 + ((lane >> 4) << 4));
    const uint32_t b_off = (uint32_t)((((lane & 7) + ((lane >> 4) & 1) * 8)) * 144 +
                                      ((lane >> 3) & 1) * 16);

    // 6 cp.async per thread per chunk (A: 1024, B: 512 transfers)
    auto issue = [&](int ch) {
        const int k0 = kbase + (ch << 6);
        const uint32_t base = sb + (uint32_t)(ch & 1) * GSTAGE;
#pragma unroll
        for (int t = 0; t < 4; t++) {
            int id = t * 256 + tid;
            int r = id >> 3, c = id & 7;
            cp16(base + (uint32_t)(r * 144 + c * 16),
                 A + (size_t)(bm + r) * K + k0 + c * 8);
        }
#pragma unroll
        for (int t = 0; t < 2; t++) {
            int id = t * 256 + tid;
            int r = id >> 3, c = id & 7;
            cp16(base + GARR_A + (uint32_t)(r * 144 + c * 16),
                 Bw + (size_t)(nb + r) * K + k0 + c * 8);
        }
        CP_COMMIT();
    };

    issue(0);
    for (int ch = 0; ch < nchunks; ch++) {
        if (ch + 1 < nchunks) { issue(ch + 1); CP_WAIT1(); }
        else                  { CP_WAIT0(); }
        __syncthreads();

        const uint32_t stg = sb + (uint32_t)(ch & 1) * GSTAGE;
        const uint32_t SA = stg, SB = stg + GARR_A;

#pragma unroll
        for (int ks = 0; ks < 4; ks++) {
            const uint32_t kb = ks * 32;
            uint32_t ah[2][4], bb[2][4];
            LDSM4(ah[0], SA + a_off + (wm) * 144 + kb);
            LDSM4(ah[1], SA + a_off + (wm + 16) * 144 + kb);
            LDSM4(bb[0], SB + b_off + (wn) * 144 + kb);
            LDSM4(bb[1], SB + b_off + (wn + 16) * 144 + kb);
#pragma unroll
            for (int mf = 0; mf < 2; mf++)
#pragma unroll
                for (int j = 0; j < 4; j++)
                    mma_f16(acc[mf][j], ah[mf][0], ah[mf][1], ah[mf][2], ah[mf][3],
                            bb[j >> 1][(j & 1) * 2], bb[j >> 1][(j & 1) * 2 + 1]);
        }
        // trailing sync only needed if iteration ch+1 will issue chunk ch+2
        if (ch + 2 < nchunks) __syncthreads();
    }

    // ---- epilogue
#pragma unroll
    for (int mf = 0; mf < 2; mf++) {
        const int r0g = bm + wm + mf * 16 + gid;
        const int r1g = r0g + 8;
#pragma unroll
        for (int j = 0; j < 4; j++) {
            const int cl = wn + j * 8 + qd * 2;
            float2 bs;
            if (MODE == 2 && kz != 0) bs = make_float2(0.f, 0.f);
            else bs = *(const float2*)(bias + nb + cl);
            float v00 = acc[mf][j][0] + bs.x, v01 = acc[mf][j][1] + bs.y;
            float v10 = acc[mf][j][2] + bs.x, v11 = acc[mf][j][3] + bs.y;
            if (MODE != 2) {
                v00 = fmaxf(v00, 0.f); v01 = fmaxf(v01, 0.f);
                v10 = fmaxf(v10, 0.f); v11 = fmaxf(v11, 0.f);
            }
            if (MODE == 0) {
                const int which = nt >> 1;
                const int mc = (nt & 1) * 64 + cl;
                size_t o0 = (size_t)r0g * 128 + mc;
                size_t o1 = (size_t)r1g * 128 + mc;
                if (which == 0) {
                    *(uint32_t*)(qh + o0) = f16x2(v00 * QSCALE, v01 * QSCALE);
                    *(uint32_t*)(qh + o1) = f16x2(v10 * QSCALE, v11 * QSCALE);
                } else if (which == 1) {
                    *(uint32_t*)(kk + o0) = f16x2(v00, v01);
                    *(uint32_t*)(kk + o1) = f16x2(v10, v11);
                } else {
                    *(uint32_t*)(vv + o0) = f16x2(v00, v01);
                    *(uint32_t*)(vv + o1) = f16x2(v10, v11);
                }
            } else if (MODE == 1) {
                size_t o0 = (size_t)r0g * ldc + nb + cl;
                size_t o1 = (size_t)r1g * ldc + nb + cl;
                *(uint32_t*)(oh + o0) = f16x2(v00, v01);
                *(uint32_t*)(oh + o1) = f16x2(v10, v11);
            } else {
                float* C = of + (size_t)kz * (Mrows * Dn);
                *(float2*)(C + (size_t)r0g * ldc + nb + cl) = make_float2(v00, v01);
                *(float2*)(C + (size_t)r1g * ldc + nb + cl) = make_float2(v10, v11);
            }
        }
    }
}

// ============================================================================
// Flash attention (R10 exact): 3-stage K/V ring, one sync/tile, all-f16
// single-pass, Q pre-scaled, shifted (-8) no-max softmax via ex2.f16x2,
// l via MMA ones. 256 threads, 128 queries/CTA, 2 CTAs/SM.
// smem: 3 stages x (K 3072 + V 3072) = 18432 B
// ============================================================================
#define AARR 3072
#define ASTG (2 * AARR)
#define ONES_H2 0x3C003C00u

__global__ __launch_bounds__(256, 2)
void attn_mma(const __half* __restrict__ Qg, const __half* __restrict__ Kg,
              const __half* __restrict__ Vg, float* __restrict__ O) {
    static __shared__ __align__(16) char sm[3 * ASTG];
    const uint32_t sb = smem_u32(sm);

    const int b = blockIdx.z, h = blockIdx.y, q0 = blockIdx.x * 128;
    const int tid = threadIdx.x, lane = tid & 31, w = tid >> 5;
    const int gid = lane >> 2, qd = lane & 3;

    const uint32_t kb_off = (uint32_t)(((lane & 7) + ((lane >> 4) & 1) * 8) * 48 +
                                       ((lane >> 3) & 1) * 16);
    const uint32_t vb_off = (uint32_t)(((lane & 7) + ((lane >> 3) & 1) * 8) * 48 +
                                       ((lane >> 4) & 1) * 16);

    // ---- Q fragments (pre-scaled f16 pairs)
    uint32_t aq[4];
    {
        const int r0 = q0 + w * 16 + gid;
        const int c0 = h * 16 + qd * 2;
        const __half* q0p = Qg + (size_t)(b * Sn + r0) * Dn;
        const __half* q1p = q0p + (size_t)8 * Dn;
        aq[0] = *(const uint32_t*)(q0p + c0);
        aq[1] = *(const uint32_t*)(q1p + c0);
        aq[2] = *(const uint32_t*)(q0p + c0 + 8);
        aq[3] = *(const uint32_t*)(q1p + c0 + 8);
    }

    // 256 cp.async per 64-key tile: K 128 + V 128 (1 per thread)
    auto issue = [&](int kt) {
        const int kbase = kt * 64;
        const uint32_t base = sb + (uint32_t)(kt % 3) * ASTG;
        int arr = tid >> 7, rem = tid & 127;
        int k = rem >> 1, c = rem & 1;
        const __half* p = arr ? Vg : Kg;
        cp16(base + (uint32_t)arr * AARR + (uint32_t)(k * 48 + c * 16),
             p + (size_t)(b * Sn + kbase + k) * Dn + h * 16 + c * 8);
        CP_COMMIT();
    };

    float oacc[2][4] = {};
    float lacc[4] = {};

    issue(0);
    for (int kt = 0; kt < 16; kt++) {
        if (kt + 1 < 16) { issue(kt + 1); CP_WAIT1(); }
        else             { CP_WAIT0(); }
        __syncthreads();   // single sync per tile (3-stage ring: no reuse hazard)

        const uint32_t stg = sb + (uint32_t)(kt % 3) * ASTG;
        const uint32_t sK = stg, sV = stg + AARR;

        // ---- QK^T (1 pass); accumulator pre-shifted by -8 (log2 domain)
        float sacc[8][4];
#pragma unroll
        for (int j = 0; j < 8; j++)
#pragma unroll
            for (int c = 0; c < 4; c++) sacc[j][c] = -8.f;
        {
            uint32_t bb[4][4];
#pragma unroll
            for (int p = 0; p < 4; p++) LDSM4(bb[p], sK + kb_off + p * 16 * 48);
#pragma unroll
            for (int j = 0; j < 8; j++)
                mma_f16(sacc[j], aq[0], aq[1], aq[2], aq[3],
                        bb[j >> 1][(j & 1) * 2], bb[j >> 1][(j & 1) * 2 + 1]);
        }

        // ---- P = 2^(s-8) as packed f16x2 (A-frag order)
        uint32_t ap[4][4];
#pragma unroll
        for (int t = 0; t < 4; t++) {
            const int e0 = 2 * t, e1 = 2 * t + 1;
            ap[t][0] = ex2h2(f16x2(sacc[e0][0], sacc[e0][1]));
            ap[t][1] = ex2h2(f16x2(sacc[e0][2], sacc[e0][3]));
            ap[t][2] = ex2h2(f16x2(sacc[e1][0], sacc[e1][1]));
            ap[t][3] = ex2h2(f16x2(sacc[e1][2], sacc[e1][3]));
        }

        // ---- l += P @ ones (row sums via MMA)
#pragma unroll
        for (int t = 0; t < 4; t++)
            mma_f16(lacc, ap[t][0], ap[t][1], ap[t][2], ap[t][3], ONES_H2, ONES_H2);

        // ---- PV (1 pass)
        {
            uint32_t vb[4][4];
#pragma unroll
            for (int t = 0; t < 4; t++) LDSM4T(vb[t], sV + vb_off + t * 16 * 48);
#pragma unroll
            for (int t = 0; t < 4; t++) {
                mma_f16(oacc[0], ap[t][0], ap[t][1], ap[t][2], ap[t][3],
                        vb[t][0], vb[t][1]);
                mma_f16(oacc[1], ap[t][0], ap[t][1], ap[t][2], ap[t][3],
                        vb[t][2], vb[t][3]);
            }
        }
    }

    // ---- write O (lacc cols are replicated row sums: [0]=row r0, [2]=row r1)
    const float inv0 = 1.f / lacc[0], inv1 = 1.f / lacc[2];
    const int r0 = q0 + w * 16 + gid, r1 = r0 + 8;
    const int c = h * 16 + qd * 2;
#pragma unroll
    for (int nf = 0; nf < 2; nf++) {
        *(float2*)&O[(size_t)(b * Sn + r0) * Dn + c + nf * 8] =
            make_float2(oacc[nf][0] * inv0, oacc[nf][1] * inv0);
        *(float2*)&O[(size_t)(b * Sn + r1) * Dn + c + nf * 8] =
            make_float2(oacc[nf][2] * inv1, oacc[nf][3] * inv1);
    }
}

// ============================================================================
// Residual add + LayerNorm (warp-per-row); NPART partial fp32 buffers summed.
// ============================================================================
template <int NPART>
__global__ __launch_bounds__(256)
void add_ln_kernel(const float* __restrict__ inp, float* __restrict__ x,
                   __half* __restrict__ xh,
                   const float* __restrict__ gam, const float* __restrict__ bet,
                   float eps) {
    const int lane = threadIdx.x & 31;
    const int row = blockIdx.x * 8 + (threadIdx.x >> 5);
    const int c0 = lane * 4;
    const size_t base = (size_t)row * Dn + c0;

    float4 a = *(const float4*)&inp[base];
#pragma unroll
    for (int p = 1; p < NPART; p++) {
        float4 ap = *(const float4*)&inp[(size_t)p * (Mrows * Dn) + base];
        a.x += ap.x; a.y += ap.y; a.z += ap.z; a.w += ap.w;
    }
    float4 bx = *(const float4*)&x[base];
    float v[4] = {a.x + bx.x, a.y + bx.y, a.z + bx.z, a.w + bx.w};

    float s = v[0] + v[1] + v[2] + v[3];
#pragma unroll
    for (int o = 16; o > 0; o >>= 1) s += __shfl_xor_sync(0xffffffffu, s, o);
    const float mu = s * (1.f / Dn);

    float d[4] = {v[0] - mu, v[1] - mu, v[2] - mu, v[3] - mu};
    float s2 = d[0] * d[0] + d[1] * d[1] + d[2] * d[2] + d[3] * d[3];
#pragma unroll
    for (int o = 16; o > 0; o >>= 1) s2 += __shfl_xor_sync(0xffffffffu, s2, o);
    const float r = rsqrtf(s2 * (1.f / Dn) + eps);

    float4 g = *(const float4*)&gam[c0];
    float4 be = *(const float4*)&bet[c0];
    float y0 = fmaf(g.x * d[0], r, be.x);
    float y1 = fmaf(g.y * d[1], r, be.y);
    float y2 = fmaf(g.z * d[2], r, be.z);
    float y3 = fmaf(g.w * d[3], r, be.w);

    *(float4*)&x[base] = make_float4(y0, y1, y2, y3);
    *(uint32_t*)&xh[base]     = f16x2(y0, y1);
    *(uint32_t*)&xh[base + 2] = f16x2(y2, y3);
}

// ============================================================================
// Classifier: warp per row, N=6 (fp32, exact)
// ============================================================================
__global__ __launch_bounds__(256)
void classifier_kernel(const float* __restrict__ x, const float* __restrict__ W,
                       const float* __restrict__ bias, float* __restrict__ out) {
    const int warp = threadIdx.x >> 5;
    const int lane = threadIdx.x & 31;
    const int row = blockIdx.x * 8 + warp;

    float acc[NCn] = {};
    for (int d = lane; d < Dn; d += 32) {
        float xv = x[(size_t)row * Dn + d];
#pragma unroll
        for (int c = 0; c < NCn; c++) acc[c] = fmaf(xv, W[d * NCn + c], acc[c]);
    }
#pragma unroll
    for (int c = 0; c < NCn; c++) {
#pragma unroll
        for (int o = 16; o > 0; o >>= 1)
            acc[c] += __shfl_down_sync(0xffffffffu, acc[c], o);
    }
    if (lane == 0) {
#pragma unroll
        for (int c = 0; c < NCn; c++) out[(size_t)row * NCn + c] = acc[c] + bias[c];
    }
}

// ============================================================================
// kernel_launch
// ============================================================================
extern "C" void kernel_launch(void* const* d_in, const int* in_sizes, int n_in,
                              void* d_out, int out_size) {
    const float* x    = (const float*)d_in[0];
    const float* Wq   = (const float*)d_in[1];
    const float* bq   = (const float*)d_in[2];
    const float* Wk   = (const float*)d_in[3];
    const float* bk   = (const float*)d_in[4];
    const float* Wv   = (const float*)d_in[5];
    const float* bv   = (const float*)d_in[6];
    const float* ln1g = (const float*)d_in[7];
    const float* ln1b = (const float*)d_in[8];
    const float* W1   = (const float*)d_in[9];
    const float* b1   = (const float*)d_in[10];
    const float* W2   = (const float*)d_in[11];
    const float* b2   = (const float*)d_in[12];
    const float* ln2g = (const float*)d_in[13];
    const float* ln2b = (const float*)d_in[14];
    const float* Wout = (const float*)d_in[15];
    const float* bout = (const float*)d_in[16];
    float* out = (float*)d_out;

    float *gx, *go, *gopart, *gbqkv;
    __half *gxh, *gq, *gk, *gv, *gh;
    __half *wqkv, *w1, *w2;
    cudaGetSymbolAddress((void**)&gx, g_x);
    cudaGetSymbolAddress((void**)&go, g_o);
    cudaGetSymbolAddress((void**)&gopart, g_opart);
    cudaGetSymbolAddress((void**)&gxh, g_xh);
    cudaGetSymbolAddress((void**)&gq, g_q);
    cudaGetSymbolAddress((void**)&gk, g_k);
    cudaGetSymbolAddress((void**)&gv, g_v);
    cudaGetSymbolAddress((void**)&gh, g_h);
    cudaGetSymbolAddress((void**)&wqkv, g_wqkv);
    cudaGetSymbolAddress((void**)&w1, g_w1);
    cudaGetSymbolAddress((void**)&w2, g_w2);
    cudaGetSymbolAddress((void**)&gbqkv, g_bqkv);

    const int SMEM_GEMM = 2 * GSTAGE;   // 55296
    cudaFuncSetAttribute(gemm_mma<0>, cudaFuncAttributeMaxDynamicSharedMemorySize, SMEM_GEMM);
    cudaFuncSetAttribute(gemm_mma<1>, cudaFuncAttributeMaxDynamicSharedMemorySize, SMEM_GEMM);
    cudaFuncSetAttribute(gemm_mma<2>, cudaFuncAttributeMaxDynamicSharedMemorySize, SMEM_GEMM);

    prep_weights<<<(PREP_TOTAL + 255) / 256, 256>>>(Wq, Wk, Wv, W1, W2);
    prep_bias<<<(Ln * 3 * Dn + 255) / 256, 256>>>(bq, bk, bv);
    prep_input<<<(Mrows * Dn / 4 + 255) / 256, 256>>>(x);

    const dim3 qkvGrid(6, Mrows / 128);          // 768 CTAs
    const dim3 f1Grid(8, Mrows / 128);           // 1024 CTAs
    const dim3 f2Grid(2, Mrows / 128, 2);        // 512 CTAs, split-K=2
    const dim3 attnGrid(Sn / 128, Hn, Bn);       // 1024 CTAs

    for (int l = 0; l < Ln; l++) {
        gemm_mma<0><<<qkvGrid, 256, SMEM_GEMM>>>(
            gxh, wqkv + (size_t)l * PREP_QKV, gbqkv + l * 3 * Dn,
            gq, gk, gv, nullptr, nullptr, Dn, Dn);

        attn_mma<<<attnGrid, 256>>>(gq, gk, gv, go);

        add_ln_kernel<1><<<Mrows / 8, 256>>>(go, gx, gxh,
                                             ln1g + l * Dn, ln1b + l * Dn, 1e-8f);

        gemm_mma<1><<<f1Grid, 256, SMEM_GEMM>>>(
            gxh, w1 + (size_t)l * PREP_W, b1 + l * DFFn,
            nullptr, nullptr, nullptr, gh, nullptr, Dn, DFFn);

        gemm_mma<2><<<f2Grid, 256, SMEM_GEMM>>>(
            gh, w2 + (size_t)l * PREP_W, b2 + l * Dn,
            nullptr, nullptr, nullptr, nullptr, gopart, DFFn, Dn);

        add_ln_kernel<2><<<Mrows / 8, 256>>>(gopart, gx, gxh,
                                             ln2g + l * Dn, ln2b + l * Dn, 1e-6f);
    }

    classifier_kernel<<<Mrows / 8, 256>>>(gx, Wout, bout, out);
}

// round 17
// speedup vs baseline: 1.0255x; 1.0234x over previous
#include <cuda_runtime.h>
#include <cuda_fp16.h>
#include <cstdint>

// Problem constants
#define Bn 16
#define Sn 1024
#define Dn 128
#define Hn 8
#define DHn 16
#define DFFn 512
#define Ln 3
#define NCn 6
#define Mrows (Bn * Sn)   // 16384

// ============================================================================
// Helpers
// ============================================================================
__device__ __forceinline__ uint32_t f16x2(float a, float b) {
    __half2 h = __floats2half2_rn(a, b);
    return *(uint32_t*)&h;
}
__device__ __forceinline__ uint32_t ex2h2(uint32_t x) {
    uint32_t y;
    asm("ex2.approx.f16x2 %0, %1;" : "=r"(y) : "r"(x));
    return y;
}
__device__ __forceinline__ uint32_t smem_u32(const void* p) {
    uint32_t a;
    asm("{ .reg .u64 t; cvta.to.shared.u64 t, %1; cvt.u32.u64 %0, t; }"
        : "=r"(a) : "l"(p));
    return a;
}
__device__ __forceinline__ void cp16(uint32_t dst, const void* src) {
    asm volatile("cp.async.cg.shared.global [%0], [%1], 16;"
                 :: "r"(dst), "l"(src));
}
#define CP_COMMIT() asm volatile("cp.async.commit_group;" ::: "memory")
#define CP_WAIT1()  asm volatile("cp.async.wait_group 1;" ::: "memory")
#define CP_WAIT0()  asm volatile("cp.async.wait_group 0;" ::: "memory")

__device__ __forceinline__ void mma_f16(float* d, uint32_t a0, uint32_t a1,
                                        uint32_t a2, uint32_t a3,
                                        uint32_t b0, uint32_t b1) {
    asm volatile(
        "mma.sync.aligned.m16n8k16.row.col.f32.f16.f16.f32 "
        "{%0,%1,%2,%3},{%4,%5,%6,%7},{%8,%9},{%0,%1,%2,%3};"
        : "+f"(d[0]), "+f"(d[1]), "+f"(d[2]), "+f"(d[3])
        : "r"(a0), "r"(a1), "r"(a2), "r"(a3), "r"(b0), "r"(b1));
}
#define LDSM4(r, addr) \
    asm volatile("ldmatrix.sync.aligned.m8n8.x4.shared.b16 {%0,%1,%2,%3},[%4];" \
        : "=r"((r)[0]), "=r"((r)[1]), "=r"((r)[2]), "=r"((r)[3]) : "r"(addr))
#define LDSM4T(r, addr) \
    asm volatile("ldmatrix.sync.aligned.m8n8.x4.trans.shared.b16 {%0,%1,%2,%3},[%4];" \
        : "=r"((r)[0]), "=r"((r)[1]), "=r"((r)[2]), "=r"((r)[3]) : "r"(addr))

// ============================================================================
// Device-global scratch
// ============================================================================
__device__ float  g_x[Mrows * Dn];
__device__ __half g_xh[Mrows * Dn];
__device__ __half g_q[Mrows * Dn];       // pre-scaled by 0.25*log2(e)
__device__ __half g_k[Mrows * Dn];
__device__ __half g_v[Mrows * Dn];
__device__ float  g_o[Mrows * Dn];
__device__ float  g_opart[2 * Mrows * Dn];   // ffn2 split-K=2 partials
__device__ __half g_h[Mrows * DFFn];
__device__ __half g_wqkv[Ln * 3 * Dn * Dn];   // f16, [N,K] transposed
__device__ __half g_w1[Ln * DFFn * Dn];
__device__ __half g_w2[Ln * Dn * DFFn];
__device__ float  g_bqkv[Ln * 3 * Dn];

// ============================================================================
// Prep kernels
// ============================================================================
#define PREP_QKV (3 * Dn * Dn)
#define PREP_W   (Dn * DFFn)
#define PREP_PER_LAYER (PREP_QKV + 2 * PREP_W)
#define PREP_TOTAL (Ln * PREP_PER_LAYER)

__global__ void prep_weights(const float* __restrict__ Wq, const float* __restrict__ Wk,
                             const float* __restrict__ Wv, const float* __restrict__ W1,
                             const float* __restrict__ W2) {
    int idx = blockIdx.x * blockDim.x + threadIdx.x;
    if (idx >= PREP_TOTAL) return;
    int l = idx / PREP_PER_LAYER;
    int r = idx % PREP_PER_LAYER;
    float v;
    __half* dst_arr;
    int dst;
    if (r < PREP_QKV) {
        int which = r / (Dn * Dn);
        int e = r % (Dn * Dn);
        int n = e / Dn, k = e % Dn;
        const float* W = which == 0 ? Wq : (which == 1 ? Wk : Wv);
        v = W[l * Dn * Dn + k * Dn + n];
        dst = l * PREP_QKV + which * Dn * Dn + n * Dn + k;
        dst_arr = g_wqkv;
    } else if (r < PREP_QKV + PREP_W) {
        int e = r - PREP_QKV;
        int n = e / Dn, k = e % Dn;
        v = W1[l * PREP_W + k * DFFn + n];
        dst = l * PREP_W + n * Dn + k;
        dst_arr = g_w1;
    } else {
        int e = r - PREP_QKV - PREP_W;
        int n = e / DFFn, k = e % DFFn;
        v = W2[l * PREP_W + k * Dn + n];
        dst = l * PREP_W + n * DFFn + k;
        dst_arr = g_w2;
    }
    dst_arr[dst] = __float2half_rn(v);
}

__global__ void prep_bias(const float* __restrict__ bq, const float* __restrict__ bk,
                          const float* __restrict__ bv) {
    int idx = blockIdx.x * blockDim.x + threadIdx.x;
    if (idx >= Ln * 3 * Dn) return;
    int l = idx / (3 * Dn);
    int r = idx % (3 * Dn);
    int which = r / Dn, n = r % Dn;
    const float* b = which == 0 ? bq : (which == 1 ? bk : bv);
    g_bqkv[idx] = b[l * Dn + n];
}

__global__ void prep_input(const float* __restrict__ x) {
    int i = (blockIdx.x * blockDim.x + threadIdx.x) * 4;
    float4 v = *(const float4*)&x[i];
    *(float4*)&g_x[i] = v;
    *(uint32_t*)&g_xh[i]     = f16x2(v.x, v.y);
    *(uint32_t*)&g_xh[i + 2] = f16x2(v.z, v.w);
}

// ============================================================================
// MMA GEMM: tile 128(M) x 64(N), f16 single-pass, 2-stage cp.async pipeline,
// 3 CTAs/SM (empirically optimal: 2->3 helped, 3->4 regressed).
// MODE 0 = QKV (ReLU; nt>>1: 0->Q pre-scaled / 1->K / 2->V)
// MODE 1 = FFN1 (ReLU; f16 out, ldc=512)
// MODE 2 = FFN2 (no act; split-K=2 over z, K=256/CTA; fp32 partials)
// smem: stage = A(18432)+B(9216) = 27648; 2 stages = 55296
// ============================================================================
#define GARR_A 18432
#define GARR_B 9216
#define GSTAGE (GARR_A + GARR_B)   // 27648
#define QSCALE 0.36067376022224085f   // 0.25 * log2(e)

template <int MODE>
__global__ __launch_bounds__(256, 3)
void gemm_mma(const __half* __restrict__ A, const __half* __restrict__ Bw,
              const float* __restrict__ bias,
              __half* __restrict__ qh, __half* __restrict__ kk,
              __half* __restrict__ vv,
              __half* __restrict__ oh, float* __restrict__ of,
              int K, int ldc) {
    extern __shared__ __align__(16) char smem[];
    const uint32_t sb = smem_u32(smem);

    const int tid = threadIdx.x, lane = tid & 31, wid = tid >> 5;
    const int nt = blockIdx.x;
    const int bm = blockIdx.y * 128;
    const int nb = nt * 64;
    const int kz = (MODE == 2) ? blockIdx.z : 0;
    const int kbase = (MODE == 2) ? kz * 256 : 0;
    const int nchunks = (MODE == 2) ? 4 : (K >> 6);
    const int wm = (wid & 3) * 32, wn = (wid >> 2) * 32;
    const int gid = lane >> 2, qd = lane & 3;

    float acc[2][4][4];
#pragma unroll
    for (int i = 0; i < 2; i++)
#pragma unroll
        for (int j = 0; j < 4; j++)
#pragma unroll
            for (int c = 0; c < 4; c++) acc[i][j][c] = 0.f;

    const uint32_t a_off = (uint32_t)((lane & 15) * 144 + ((lane >> 4) << 4));
    const uint32_t b_off = (uint32_t)((((lane & 7) + ((lane >> 4) & 1) * 8)) * 144 +
                                      ((lane >> 3) & 1) * 16);

    // 6 cp.async per thread per chunk (A: 1024, B: 512 transfers)
    auto issue = [&](int ch) {
        const int k0 = kbase + (ch << 6);
        const uint32_t base = sb + (uint32_t)(ch & 1) * GSTAGE;
#pragma unroll
        for (int t = 0; t < 4; t++) {
            int id = t * 256 + tid;
            int r = id >> 3, c = id & 7;
            cp16(base + (uint32_t)(r * 144 + c * 16),
                 A + (size_t)(bm + r) * K + k0 + c * 8);
        }
#pragma unroll
        for (int t = 0; t < 2; t++) {
            int id = t * 256 + tid;
            int r = id >> 3, c = id & 7;
            cp16(base + GARR_A + (uint32_t)(r * 144 + c * 16),
                 Bw + (size_t)(nb + r) * K + k0 + c * 8);
        }
        CP_COMMIT();
    };

    issue(0);
    for (int ch = 0; ch < nchunks; ch++) {
        if (ch + 1 < nchunks) { issue(ch + 1); CP_WAIT1(); }
        else                  { CP_WAIT0(); }
        __syncthreads();

        const uint32_t stg = sb + (uint32_t)(ch & 1) * GSTAGE;
        const uint32_t SA = stg, SB = stg + GARR_A;

#pragma unroll
        for (int ks = 0; ks < 4; ks++) {
            const uint32_t kb = ks * 32;
            uint32_t ah[2][4], bb[2][4];
            LDSM4(ah[0], SA + a_off + (wm) * 144 + kb);
            LDSM4(ah[1], SA + a_off + (wm + 16) * 144 + kb);
            LDSM4(bb[0], SB + b_off + (wn) * 144 + kb);
            LDSM4(bb[1], SB + b_off + (wn + 16) * 144 + kb);
#pragma unroll
            for (int mf = 0; mf < 2; mf++)
#pragma unroll
                for (int j = 0; j < 4; j++)
                    mma_f16(acc[mf][j], ah[mf][0], ah[mf][1], ah[mf][2], ah[mf][3],
                            bb[j >> 1][(j & 1) * 2], bb[j >> 1][(j & 1) * 2 + 1]);
        }
        // trailing sync only needed if iteration ch+1 will issue chunk ch+2
        if (ch + 2 < nchunks) __syncthreads();
    }

    // ---- epilogue
#pragma unroll
    for (int mf = 0; mf < 2; mf++) {
        const int r0g = bm + wm + mf * 16 + gid;
        const int r1g = r0g + 8;
#pragma unroll
        for (int j = 0; j < 4; j++) {
            const int cl = wn + j * 8 + qd * 2;
            float2 bs;
            if (MODE == 2 && kz != 0) bs = make_float2(0.f, 0.f);
            else bs = *(const float2*)(bias + nb + cl);
            float v00 = acc[mf][j][0] + bs.x, v01 = acc[mf][j][1] + bs.y;
            float v10 = acc[mf][j][2] + bs.x, v11 = acc[mf][j][3] + bs.y;
            if (MODE != 2) {
                v00 = fmaxf(v00, 0.f); v01 = fmaxf(v01, 0.f);
                v10 = fmaxf(v10, 0.f); v11 = fmaxf(v11, 0.f);
            }
            if (MODE == 0) {
                const int which = nt >> 1;
                const int mc = (nt & 1) * 64 + cl;
                size_t o0 = (size_t)r0g * 128 + mc;
                size_t o1 = (size_t)r1g * 128 + mc;
                if (which == 0) {
                    *(uint32_t*)(qh + o0) = f16x2(v00 * QSCALE, v01 * QSCALE);
                    *(uint32_t*)(qh + o1) = f16x2(v10 * QSCALE, v11 * QSCALE);
                } else if (which == 1) {
                    *(uint32_t*)(kk + o0) = f16x2(v00, v01);
                    *(uint32_t*)(kk + o1) = f16x2(v10, v11);
                } else {
                    *(uint32_t*)(vv + o0) = f16x2(v00, v01);
                    *(uint32_t*)(vv + o1) = f16x2(v10, v11);
                }
            } else if (MODE == 1) {
                size_t o0 = (size_t)r0g * ldc + nb + cl;
                size_t o1 = (size_t)r1g * ldc + nb + cl;
                *(uint32_t*)(oh + o0) = f16x2(v00, v01);
                *(uint32_t*)(oh + o1) = f16x2(v10, v11);
            } else {
                float* C = of + (size_t)kz * (Mrows * Dn);
                *(float2*)(C + (size_t)r0g * ldc + nb + cl) = make_float2(v00, v01);
                *(float2*)(C + (size_t)r1g * ldc + nb + cl) = make_float2(v10, v11);
            }
        }
    }
}

// ============================================================================
// Flash attention: 3-stage K/V ring (one sync/tile), all-f16 single-pass,
// Q pre-scaled, shifted (-8) no-max softmax via ex2.f16x2, l via MMA ones.
// 256 threads, 128 queries/CTA, 2 CTAs/SM.
// smem: 3 stages x (K 3072 + V 3072) = 18432 B
// ============================================================================
#define AARR 3072
#define ASTG (2 * AARR)
#define ONES_H2 0x3C003C00u

__global__ __launch_bounds__(256, 2)
void attn_mma(const __half* __restrict__ Qg, const __half* __restrict__ Kg,
              const __half* __restrict__ Vg, float* __restrict__ O) {
    static __shared__ __align__(16) char sm[3 * ASTG];
    const uint32_t sb = smem_u32(sm);

    const int b = blockIdx.z, h = blockIdx.y, q0 = blockIdx.x * 128;
    const int tid = threadIdx.x, lane = tid & 31, w = tid >> 5;
    const int gid = lane >> 2, qd = lane & 3;

    const uint32_t kb_off = (uint32_t)(((lane & 7) + ((lane >> 4) & 1) * 8) * 48 +
                                       ((lane >> 3) & 1) * 16);
    const uint32_t vb_off = (uint32_t)(((lane & 7) + ((lane >> 3) & 1) * 8) * 48 +
                                       ((lane >> 4) & 1) * 16);

    // ---- Q fragments (pre-scaled f16 pairs)
    uint32_t aq[4];
    {
        const int r0 = q0 + w * 16 + gid;
        const int c0 = h * 16 + qd * 2;
        const __half* q0p = Qg + (size_t)(b * Sn + r0) * Dn;
        const __half* q1p = q0p + (size_t)8 * Dn;
        aq[0] = *(const uint32_t*)(q0p + c0);
        aq[1] = *(const uint32_t*)(q1p + c0);
        aq[2] = *(const uint32_t*)(q0p + c0 + 8);
        aq[3] = *(const uint32_t*)(q1p + c0 + 8);
    }

    // 256 cp.async per 64-key tile: K 128 + V 128 (1 per thread)
    auto issue = [&](int kt) {
        const int kbase = kt * 64;
        const uint32_t base = sb + (uint32_t)(kt % 3) * ASTG;
        int arr = tid >> 7, rem = tid & 127;
        int k = rem >> 1, c = rem & 1;
        const __half* p = arr ? Vg : Kg;
        cp16(base + (uint32_t)arr * AARR + (uint32_t)(k * 48 + c * 16),
             p + (size_t)(b * Sn + kbase + k) * Dn + h * 16 + c * 8);
        CP_COMMIT();
    };

    float oacc[2][4] = {};
    float lacc[4] = {};

    issue(0);
    for (int kt = 0; kt < 16; kt++) {
        if (kt + 1 < 16) { issue(kt + 1); CP_WAIT1(); }
        else             { CP_WAIT0(); }
        __syncthreads();   // single sync per tile (3-stage ring: no reuse hazard)

        const uint32_t stg = sb + (uint32_t)(kt % 3) * ASTG;
        const uint32_t sK = stg, sV = stg + AARR;

        // ---- QK^T (1 pass); accumulator pre-shifted by -8 (log2 domain)
        float sacc[8][4];
#pragma unroll
        for (int j = 0; j < 8; j++)
#pragma unroll
            for (int c = 0; c < 4; c++) sacc[j][c] = -8.f;
        {
            uint32_t bb[4][4];
#pragma unroll
            for (int p = 0; p < 4; p++) LDSM4(bb[p], sK + kb_off + p * 16 * 48);
#pragma unroll
            for (int j = 0; j < 8; j++)
                mma_f16(sacc[j], aq[0], aq[1], aq[2], aq[3],
                        bb[j >> 1][(j & 1) * 2], bb[j >> 1][(j & 1) * 2 + 1]);
        }

        // ---- P = 2^(s-8) as packed f16x2 (A-frag order)
        uint32_t ap[4][4];
#pragma unroll
        for (int t = 0; t < 4; t++) {
            const int e0 = 2 * t, e1 = 2 * t + 1;
            ap[t][0] = ex2h2(f16x2(sacc[e0][0], sacc[e0][1]));
            ap[t][1] = ex2h2(f16x2(sacc[e0][2], sacc[e0][3]));
            ap[t][2] = ex2h2(f16x2(sacc[e1][0], sacc[e1][1]));
            ap[t][3] = ex2h2(f16x2(sacc[e1][2], sacc[e1][3]));
        }

        // ---- l += P @ ones (row sums via MMA)
#pragma unroll
        for (int t = 0; t < 4; t++)
            mma_f16(lacc, ap[t][0], ap[t][1], ap[t][2], ap[t][3], ONES_H2, ONES_H2);

        // ---- PV (1 pass)
        {
            uint32_t vb[4][4];
#pragma unroll
            for (int t = 0; t < 4; t++) LDSM4T(vb[t], sV + vb_off + t * 16 * 48);
#pragma unroll
            for (int t = 0; t < 4; t++) {
                mma_f16(oacc[0], ap[t][0], ap[t][1], ap[t][2], ap[t][3],
                        vb[t][0], vb[t][1]);
                mma_f16(oacc[1], ap[t][0], ap[t][1], ap[t][2], ap[t][3],
                        vb[t][2], vb[t][3]);
            }
        }
    }

    // ---- write O (lacc cols are replicated row sums: [0]=row r0, [2]=row r1)
    const float inv0 = 1.f / lacc[0], inv1 = 1.f / lacc[2];
    const int r0 = q0 + w * 16 + gid, r1 = r0 + 8;
    const int c = h * 16 + qd * 2;
#pragma unroll
    for (int nf = 0; nf < 2; nf++) {
        *(float2*)&O[(size_t)(b * Sn + r0) * Dn + c + nf * 8] =
            make_float2(oacc[nf][0] * inv0, oacc[nf][1] * inv0);
        *(float2*)&O[(size_t)(b * Sn + r1) * Dn + c + nf * 8] =
            make_float2(oacc[nf][2] * inv1, oacc[nf][3] * inv1);
    }
}

// ============================================================================
// Residual add + LayerNorm (warp-per-row); NPART partial fp32 buffers summed.
// ============================================================================
template <int NPART>
__global__ __launch_bounds__(256)
void add_ln_kernel(const float* __restrict__ inp, float* __restrict__ x,
                   __half* __restrict__ xh,
                   const float* __restrict__ gam, const float* __restrict__ bet,
                   float eps) {
    const int lane = threadIdx.x & 31;
    const int row = blockIdx.x * 8 + (threadIdx.x >> 5);
    const int c0 = lane * 4;
    const size_t base = (size_t)row * Dn + c0;

    float4 a = *(const float4*)&inp[base];
#pragma unroll
    for (int p = 1; p < NPART; p++) {
        float4 ap = *(const float4*)&inp[(size_t)p * (Mrows * Dn) + base];
        a.x += ap.x; a.y += ap.y; a.z += ap.z; a.w += ap.w;
    }
    float4 bx = *(const float4*)&x[base];
    float v[4] = {a.x + bx.x, a.y + bx.y, a.z + bx.z, a.w + bx.w};

    float s = v[0] + v[1] + v[2] + v[3];
#pragma unroll
    for (int o = 16; o > 0; o >>= 1) s += __shfl_xor_sync(0xffffffffu, s, o);
    const float mu = s * (1.f / Dn);

    float d[4] = {v[0] - mu, v[1] - mu, v[2] - mu, v[3] - mu};
    float s2 = d[0] * d[0] + d[1] * d[1] + d[2] * d[2] + d[3] * d[3];
#pragma unroll
    for (int o = 16; o > 0; o >>= 1) s2 += __shfl_xor_sync(0xffffffffu, s2, o);
    const float r = rsqrtf(s2 * (1.f / Dn) + eps);

    float4 g = *(const float4*)&gam[c0];
    float4 be = *(const float4*)&bet[c0];
    float y0 = fmaf(g.x * d[0], r, be.x);
    float y1 = fmaf(g.y * d[1], r, be.y);
    float y2 = fmaf(g.z * d[2], r, be.z);
    float y3 = fmaf(g.w * d[3], r, be.w);

    *(float4*)&x[base] = make_float4(y0, y1, y2, y3);
    *(uint32_t*)&xh[base]     = f16x2(y0, y1);
    *(uint32_t*)&xh[base + 2] = f16x2(y2, y3);
}

// ============================================================================
// Classifier: warp per row, N=6 (fp32, exact)
// ============================================================================
__global__ __launch_bounds__(256)
void classifier_kernel(const float* __restrict__ x, const float* __restrict__ W,
                       const float* __restrict__ bias, float* __restrict__ out) {
    const int warp = threadIdx.x >> 5;
    const int lane = threadIdx.x & 31;
    const int row = blockIdx.x * 8 + warp;

    float acc[NCn] = {};
    for (int d = lane; d < Dn; d += 32) {
        float xv = x[(size_t)row * Dn + d];
#pragma unroll
        for (int c = 0; c < NCn; c++) acc[c] = fmaf(xv, W[d * NCn + c], acc[c]);
    }
#pragma unroll
    for (int c = 0; c < NCn; c++) {
#pragma unroll
        for (int o = 16; o > 0; o >>= 1)
            acc[c] += __shfl_down_sync(0xffffffffu, acc[c], o);
    }
    if (lane == 0) {
#pragma unroll
        for (int c = 0; c < NCn; c++) out[(size_t)row * NCn + c] = acc[c] + bias[c];
    }
}

// ============================================================================
// kernel_launch
// ============================================================================
extern "C" void kernel_launch(void* const* d_in, const int* in_sizes, int n_in,
                              void* d_out, int out_size) {
    const float* x    = (const float*)d_in[0];
    const float* Wq   = (const float*)d_in[1];
    const float* bq   = (const float*)d_in[2];
    const float* Wk   = (const float*)d_in[3];
    const float* bk   = (const float*)d_in[4];
    const float* Wv   = (const float*)d_in[5];
    const float* bv   = (const float*)d_in[6];
    const float* ln1g = (const float*)d_in[7];
    const float* ln1b = (const float*)d_in[8];
    const float* W1   = (const float*)d_in[9];
    const float* b1   = (const float*)d_in[10];
    const float* W2   = (const float*)d_in[11];
    const float* b2   = (const float*)d_in[12];
    const float* ln2g = (const float*)d_in[13];
    const float* ln2b = (const float*)d_in[14];
    const float* Wout = (const float*)d_in[15];
    const float* bout = (const float*)d_in[16];
    float* out = (float*)d_out;

    float *gx, *go, *gopart, *gbqkv;
    __half *gxh, *gq, *gk, *gv, *gh;
    __half *wqkv, *w1, *w2;
    cudaGetSymbolAddress((void**)&gx, g_x);
    cudaGetSymbolAddress((void**)&go, g_o);
    cudaGetSymbolAddress((void**)&gopart, g_opart);
    cudaGetSymbolAddress((void**)&gxh, g_xh);
    cudaGetSymbolAddress((void**)&gq, g_q);
    cudaGetSymbolAddress((void**)&gk, g_k);
    cudaGetSymbolAddress((void**)&gv, g_v);
    cudaGetSymbolAddress((void**)&gh, g_h);
    cudaGetSymbolAddress((void**)&wqkv, g_wqkv);
    cudaGetSymbolAddress((void**)&w1, g_w1);
    cudaGetSymbolAddress((void**)&w2, g_w2);
    cudaGetSymbolAddress((void**)&gbqkv, g_bqkv);

    const int SMEM_GEMM = 2 * GSTAGE;   // 55296
    cudaFuncSetAttribute(gemm_mma<0>, cudaFuncAttributeMaxDynamicSharedMemorySize, SMEM_GEMM);
    cudaFuncSetAttribute(gemm_mma<1>, cudaFuncAttributeMaxDynamicSharedMemorySize, SMEM_GEMM);
    cudaFuncSetAttribute(gemm_mma<2>, cudaFuncAttributeMaxDynamicSharedMemorySize, SMEM_GEMM);

    prep_weights<<<(PREP_TOTAL + 255) / 256, 256>>>(Wq, Wk, Wv, W1, W2);
    prep_bias<<<(Ln * 3 * Dn + 255) / 256, 256>>>(bq, bk, bv);
    prep_input<<<(Mrows * Dn / 4 + 255) / 256, 256>>>(x);

    const dim3 qkvGrid(6, Mrows / 128);          // 768 CTAs
    const dim3 f1Grid(8, Mrows / 128);           // 1024 CTAs
    const dim3 f2Grid(2, Mrows / 128, 2);        // 512 CTAs, split-K=2
    const dim3 attnGrid(Sn / 128, Hn, Bn);       // 1024 CTAs

    for (int l = 0; l < Ln; l++) {
        gemm_mma<0><<<qkvGrid, 256, SMEM_GEMM>>>(
            gxh, wqkv + (size_t)l * PREP_QKV, gbqkv + l * 3 * Dn,
            gq, gk, gv, nullptr, nullptr, Dn, Dn);

        attn_mma<<<attnGrid, 256>>>(gq, gk, gv, go);

        add_ln_kernel<1><<<Mrows / 8, 256>>>(go, gx, gxh,
                                             ln1g + l * Dn, ln1b + l * Dn, 1e-8f);

        gemm_mma<1><<<f1Grid, 256, SMEM_GEMM>>>(
            gxh, w1 + (size_t)l * PREP_W, b1 + l * DFFn,
            nullptr, nullptr, nullptr, gh, nullptr, Dn, DFFn);

        gemm_mma<2><<<f2Grid, 256, SMEM_GEMM>>>(
            gh, w2 + (size_t)l * PREP_W, b2 + l * Dn,
            nullptr, nullptr, nullptr, nullptr, gopart, DFFn, Dn);

        add_ln_kernel<2><<<Mrows / 8, 256>>>(gopart, gx, gxh,
                                             ln2g + l * Dn, ln2b + l * Dn, 1e-6f);
    }

    classifier_kernel<<<Mrows / 8, 256>>>(gx, Wout, bout, out);
}